// round 7
// baseline (speedup 1.0000x reference)
#include <cuda_runtime.h>
#include <cuda_fp16.h>
#include <cstdint>
#include <cstddef>
#include <math.h>

// ---------------- problem constants ----------------
#define BTOK  16384
#define IND   512
#define HIDD  2048
#define NEXP  8
#define NTOP  4

// ---------------- tiling ----------------
#define TM      128               // tokens per block
#define TN      128               // hidden cols per block
#define KBPST   4                 // K=64 per stage
#define NST     3
#define NKCH    8                 // 512 / 64 k-chunks per tile
#define HTILES  (HIDD / TN)       // 16
#define NTHR    256

// stage sizes
// A stage: 128 rows x 128B (row-major fp16, XOR-swizzled chunks) = 16384 B
// B stage: 16 h8-tiles x 4 kb x 32 lanes x 8B (packed frags)     = 16384 B
#define A_BYTES 16384
#define B_BYTES 16384
#define STAGE_BYTES (A_BYTES + B_BYTES)       // 32768
#define EPI_OFF     (NST * STAGE_BYTES)       // 98304
#define SMEM_TOTAL  (EPI_OFF + 4096)          // 102400 (2 CTAs/SM)

#define B_TILE_BYTES  8192     // one 8-col h-tile: 32 kb x 32 lanes x 8B

// ---------------- device scratch ----------------
__device__ __align__(1024) __half   g_xc16[(size_t)NEXP * BTOK * IND];    // compacted x rows, row-major fp16
__device__ __align__(1024) uint32_t g_w1u[(size_t)NEXP * HIDD * IND / 2]; // W1 packed B-frags (half2)
__device__ int   g_cnt[NEXP];
__device__ int   g_sel[BTOK * NTOP];
__device__ int   g_slot[BTOK * NTOP];
__device__ float g_g4[BTOK * NTOP];
__device__ float g_part[(size_t)NEXP * BTOK * HTILES];

// ---------------- helpers ----------------
__device__ __forceinline__ void cp_async16(uint32_t saddr, const void* gaddr) {
    asm volatile("cp.async.cg.shared.global [%0], [%1], 16;" :: "r"(saddr), "l"(gaddr) : "memory");
}
__device__ __forceinline__ uint32_t smem_u32(const void* p) {
    uint32_t a;
    asm("{ .reg .u64 t; cvta.to.shared.u64 t, %1; cvt.u32.u64 %0, t; }" : "=r"(a) : "l"(p));
    return a;
}
__device__ __forceinline__ void mma_f16(float* c, const uint32_t* a, const uint32_t* b) {
    asm volatile(
        "mma.sync.aligned.m16n8k16.row.col.f32.f16.f16.f32 "
        "{%0,%1,%2,%3}, {%4,%5,%6,%7}, {%8,%9}, {%0,%1,%2,%3};"
        : "+f"(c[0]), "+f"(c[1]), "+f"(c[2]), "+f"(c[3])
        : "r"(a[0]), "r"(a[1]), "r"(a[2]), "r"(a[3]), "r"(b[0]), "r"(b[1]));
}
__device__ __forceinline__ void ldmx4(uint32_t* r, uint32_t saddr) {
    asm volatile("ldmatrix.sync.aligned.m8n8.x4.shared.b16 {%0,%1,%2,%3}, [%4];"
        : "=r"(r[0]), "=r"(r[1]), "=r"(r[2]), "=r"(r[3]) : "r"(saddr));
}

// ============================================================
// kernel 0: zero counters
// ============================================================
__global__ void k_zero() {
    if (threadIdx.x < NEXP) g_cnt[threadIdx.x] = 0;
}

// ============================================================
// kernel 1: W1 -> packed fp16 B-fragment layout (unchanged)
// ============================================================
__global__ void k_transpose(const float* __restrict__ W1) {
    __shared__ float tile[16][129];
    int hc = blockIdx.x;      // 128-h chunk
    int kb = blockIdx.y;      // K=16 block (32 of them)
    int e  = blockIdx.z;
    int tid = threadIdx.x;

    #pragma unroll
    for (int it = 0; it < 8; ++it) {
        int idx = tid + it * 256;
        int kr = idx >> 7, hf = idx & 127;
        tile[kr][hf] = W1[((size_t)e * IND + kb * 16 + kr) * HIDD + hc * 128 + hf];
    }
    __syncthreads();

    size_t base2 = (size_t)e * (HIDD * IND / 2);
    #pragma unroll
    for (int it = 0; it < 4; ++it) {
        int w    = tid + it * 256;
        int h8l  = w >> 6;
        int rem  = w & 63;
        int lane = rem >> 1, rj = rem & 1;
        int grp  = lane >> 2, qid = lane & 3;
        int hl   = h8l * 8 + grp;
        int k0   = rj * 8 + qid * 2;
        __half2 v = __floats2half2_rn(tile[k0][hl], tile[k0 + 1][hl]);
        g_w1u[base2 + (size_t)(hc * 16 + h8l) * 2048 + (kb * 32 + lane) * 2 + rj]
            = *(uint32_t*)&v;
    }
}

// ============================================================
// kernel 2: gating + top-4 + softmax + coalesced row scatter
// ============================================================
__global__ void k_gate(const float* __restrict__ x, const float* __restrict__ wg) {
    int warp = blockIdx.x * (blockDim.x >> 5) + (threadIdx.x >> 5);
    int lane = threadIdx.x & 31;
    if (warp >= BTOK) return;
    const float* xr = x + (size_t)warp * IND;

    float acc[NEXP];
    #pragma unroll
    for (int e = 0; e < NEXP; ++e) acc[e] = 0.f;
    for (int i = lane; i < IND; i += 32) {
        float xv = xr[i];
        #pragma unroll
        for (int e = 0; e < NEXP; ++e) acc[e] = fmaf(xv, wg[i * NEXP + e], acc[e]);
    }
    #pragma unroll
    for (int off = 16; off > 0; off >>= 1) {
        #pragma unroll
        for (int e = 0; e < NEXP; ++e)
            acc[e] += __shfl_xor_sync(0xFFFFFFFFu, acc[e], off);
    }

    // top-4: strict '>' keeps lowest index on ties (matches jax.lax.top_k)
    int   sel[NTOP];
    float val[NTOP];
    bool  used[NEXP];
    #pragma unroll
    for (int e = 0; e < NEXP; ++e) used[e] = false;
    #pragma unroll
    for (int k = 0; k < NTOP; ++k) {
        float best = -1e30f; int be = 0;
        #pragma unroll
        for (int e = 0; e < NEXP; ++e)
            if (!used[e] && acc[e] > best) { best = acc[e]; be = e; }
        used[be] = true; sel[k] = be; val[k] = best;
    }
    float s = 0.f, gt[NTOP];
    #pragma unroll
    for (int k = 0; k < NTOP; ++k) { gt[k] = expf(val[k] - val[0]); s += gt[k]; }
    float inv = 1.f / s;
    #pragma unroll
    for (int k = 0; k < NTOP; ++k) gt[k] *= inv;

    int slot[NTOP];
    if (lane == 0) {
        #pragma unroll
        for (int k = 0; k < NTOP; ++k) slot[k] = atomicAdd(&g_cnt[sel[k]], 1);
    }
    #pragma unroll
    for (int k = 0; k < NTOP; ++k) slot[k] = __shfl_sync(0xFFFFFFFFu, slot[k], 0);

    if (lane < NTOP) {
        g_sel[warp * NTOP + lane]  = sel[lane];
        g_slot[warp * NTOP + lane] = slot[lane];
        g_g4[warp * NTOP + lane]   = gt[lane];
    }

    // lane owns halfs [lane*16, lane*16+16): pack once, store 2x16B per expert
    uint32_t hw[8];
    #pragma unroll
    for (int j = 0; j < 8; ++j) {
        __half2 v = __floats2half2_rn(xr[lane * 16 + 2 * j], xr[lane * 16 + 2 * j + 1]);
        hw[j] = *(uint32_t*)&v;
    }
    uint4 v0 = make_uint4(hw[0], hw[1], hw[2], hw[3]);
    uint4 v1 = make_uint4(hw[4], hw[5], hw[6], hw[7]);

    #pragma unroll
    for (int kk = 0; kk < NTOP; ++kk) {
        __half* dst = g_xc16 + ((size_t)sel[kk] * BTOK + slot[kk]) * IND + lane * 16;
        ((uint4*)dst)[0] = v0;
        ((uint4*)dst)[1] = v1;
    }
}

// ============================================================
// kernel 3: persistent expert GEMM fp16 (fc1 + relu + fc2-partial)
// grid = 2 * numSMs, 256 threads, 2 CTAs/SM
// ============================================================
__device__ __forceinline__ void load_chunk(uint32_t sb, int slot, int kt, int tid,
                                           const __half* Ag, const char* Bg) {
    uint32_t abase = sb + (uint32_t)slot * STAGE_BYTES;
    uint32_t bbase = abase + A_BYTES;
    // A: 128 rows x 128B, XOR-swizzled 16B chunks
    #pragma unroll
    for (int it = 0; it < 4; ++it) {
        int c   = tid + it * NTHR;
        int row = c >> 3, ch = c & 7;
        cp_async16(abase + (uint32_t)row * 128 + (uint32_t)((ch ^ (row & 7)) << 4),
                   Ag + (size_t)row * IND + kt * 64 + ch * 8);
    }
    // B: packed frags, 1024 x 16B
    #pragma unroll
    for (int it = 0; it < 4; ++it) {
        int c    = tid + it * NTHR;
        int tile = c >> 6, rem = c & 63;
        cp_async16(bbase + (uint32_t)c * 16,
                   Bg + (size_t)tile * B_TILE_BYTES + kt * 1024 + rem * 16);
    }
    asm volatile("cp.async.commit_group;" ::: "memory");
}

__global__ void __launch_bounds__(NTHR, 2)
k_expert(const float* __restrict__ W2, const float* __restrict__ b1) {
    extern __shared__ char smem[];
    const int tid  = threadIdx.x;
    const int wid  = tid >> 5;
    const int lane = tid & 31;
    const int wm   = wid >> 2;       // 0..1 : rows wm*64
    const int wn   = wid & 3;        // 0..3 : cols wn*32
    const int grp  = lane >> 2;
    const int qid  = lane & 3;

    uint32_t sb = smem_u32(smem);
    float* red = (float*)(smem + EPI_OFF);          // 128*4 floats
    float* w2s = (float*)(smem + EPI_OFF + 2048);   // 128 floats
    float* b1s = (float*)(smem + EPI_OFF + 2560);   // 128 floats
    int*   cum = (int*)  (smem + EPI_OFF + 3072);   // 9 ints

    if (tid == 0) {
        int c = 0;
        cum[0] = 0;
        #pragma unroll
        for (int e = 0; e < NEXP; ++e) {
            c += ((g_cnt[e] + TM - 1) / TM) * HTILES;
            cum[e + 1] = c;
        }
    }
    __syncthreads();
    const int nt_total = cum[NEXP];
    const int stride   = gridDim.x;

    // ldmatrix per-thread geometry
    const int mat  = lane >> 3, rin = lane & 7;
    const uint32_t arow_off = (uint32_t)(wm * 64 + (mat & 1) * 8 + rin) * 128;
    const int khalf = mat >> 1;

    // ---- load cursor ----
    int lt = blockIdx.x;     // tile id being loaded
    int lkt = 0;
    const __half* LAg = nullptr;
    const char*   LBg = nullptr;
    if (lt < nt_total) {
        int e = 0;
        while (lt >= cum[e + 1]) ++e;
        int loc = lt - cum[e];
        LAg = g_xc16 + ((size_t)e * BTOK + (loc >> 4) * TM) * IND;
        LBg = (const char*)g_w1u + (size_t)e * (HIDD * IND * 2)
            + (size_t)(loc & 15) * (TN / 8) * B_TILE_BYTES;
    }
    int ls = 0;   // load slot 0..2

    // prime 2 chunks
    #pragma unroll
    for (int p = 0; p < 2; ++p) {
        if (lt < nt_total) {
            load_chunk(sb, ls, lkt, tid, LAg, LBg);
            if (++ls == NST) ls = 0;
            if (++lkt == NKCH) {
                lkt = 0; lt += stride;
                if (lt < nt_total) {
                    int e = 0;
                    while (lt >= cum[e + 1]) ++e;
                    int loc = lt - cum[e];
                    LAg = g_xc16 + ((size_t)e * BTOK + (loc >> 4) * TM) * IND;
                    LBg = (const char*)g_w1u + (size_t)e * (HIDD * IND * 2)
                        + (size_t)(loc & 15) * (TN / 8) * B_TILE_BYTES;
                }
            }
        } else {
            asm volatile("cp.async.commit_group;" ::: "memory");
        }
    }

    int cs = 0;   // compute slot 0..2

    // ---- persistent tile loop ----
    for (int ct = blockIdx.x; ct < nt_total; ct += stride) {
        int e = 0;
        while (ct >= cum[e + 1]) ++e;
        int loc = ct - cum[e];
        int m0  = (loc >> 4) * TM;
        int ht  = loc & 15;

        float acc[4][4][4];
        #pragma unroll
        for (int mt = 0; mt < 4; ++mt)
            #pragma unroll
            for (int nt = 0; nt < 4; ++nt)
                #pragma unroll
                for (int r = 0; r < 4; ++r) acc[mt][nt][r] = 0.f;

        for (int kt = 0; kt < NKCH; ++kt) {
            asm volatile("cp.async.wait_group 1;" ::: "memory");
            __syncthreads();

            // issue next load (keeps exactly one commit per iteration)
            if (lt < nt_total) {
                load_chunk(sb, ls, lkt, tid, LAg, LBg);
                if (++ls == NST) ls = 0;
                if (++lkt == NKCH) {
                    lkt = 0; lt += stride;
                    if (lt < nt_total) {
                        int ee = 0;
                        while (lt >= cum[ee + 1]) ++ee;
                        int lloc = lt - cum[ee];
                        LAg = g_xc16 + ((size_t)ee * BTOK + (lloc >> 4) * TM) * IND;
                        LBg = (const char*)g_w1u + (size_t)ee * (HIDD * IND * 2)
                            + (size_t)(lloc & 15) * (TN / 8) * B_TILE_BYTES;
                    }
                }
            } else {
                asm volatile("cp.async.commit_group;" ::: "memory");
            }

            uint32_t abase = sb + (uint32_t)cs * STAGE_BYTES + arow_off;
            const uint2* sB = (const uint2*)(smem + (size_t)cs * STAGE_BYTES + A_BYTES);

            #pragma unroll
            for (int ks = 0; ks < KBPST; ++ks) {         // 4 K=16 steps
                uint32_t af[4][4];
                uint2 bf[4];
                uint32_t achunk = (uint32_t)(((ks << 1) | khalf) ^ rin) << 4;
                #pragma unroll
                for (int mt = 0; mt < 4; ++mt)
                    ldmx4(af[mt], abase + (uint32_t)mt * 2048 + achunk);
                #pragma unroll
                for (int nt = 0; nt < 4; ++nt)
                    bf[nt] = sB[((wn * 4 + nt) * 4 + ks) * 32 + lane];
                #pragma unroll
                for (int mt = 0; mt < 4; ++mt)
                    #pragma unroll
                    for (int nt = 0; nt < 4; ++nt)
                        mma_f16(acc[mt][nt], af[mt], (const uint32_t*)&bf[nt]);
            }
            if (++cs == NST) cs = 0;
        }

        // ---- fused epilogue: relu(h + b1) . W2 ----
        if (tid < TN) {
            w2s[tid] = W2[(size_t)e * HIDD + ht * TN + tid];
            b1s[tid] = b1[(size_t)e * HIDD + ht * TN + tid];
        }
        __syncthreads();

        #pragma unroll
        for (int mt = 0; mt < 4; ++mt) {
            #pragma unroll
            for (int rr = 0; rr < 2; ++rr) {
                int row = wm * 64 + mt * 16 + grp + rr * 8;
                float v = 0.f;
                #pragma unroll
                for (int nt = 0; nt < 4; ++nt) {
                    int col = wn * 32 + nt * 8 + qid * 2;
                    float h0 = fmaxf(acc[mt][nt][rr * 2 + 0] + b1s[col], 0.f);
                    float h1 = fmaxf(acc[mt][nt][rr * 2 + 1] + b1s[col + 1], 0.f);
                    v = fmaf(h0, w2s[col], v);
                    v = fmaf(h1, w2s[col + 1], v);
                }
                v += __shfl_down_sync(0xFFFFFFFFu, v, 2);
                v += __shfl_down_sync(0xFFFFFFFFu, v, 1);
                if (qid == 0) red[row * 4 + wn] = v;
            }
        }
        __syncthreads();

        if (tid < TM) {
            float p = red[tid * 4 + 0] + red[tid * 4 + 1] + red[tid * 4 + 2] + red[tid * 4 + 3];
            g_part[((size_t)e * BTOK + m0 + tid) * HTILES + ht] = p;
        }
        __syncthreads();
    }
}

// ============================================================
// kernel 4: weighted combine
// ============================================================
__global__ void k_combine(float* __restrict__ out, const float* __restrict__ b2) {
    int t = blockIdx.x * blockDim.x + threadIdx.x;
    if (t >= BTOK) return;
    float y = 0.f;
    #pragma unroll
    for (int k = 0; k < NTOP; ++k) {
        int   e = g_sel[t * NTOP + k];
        int   s = g_slot[t * NTOP + k];
        float g = g_g4[t * NTOP + k];
        float p = b2[e];
        const float* pp = &g_part[((size_t)e * BTOK + s) * HTILES];
        #pragma unroll
        for (int h = 0; h < HTILES; ++h) p += pp[h];
        y = fmaf(g, p, y);
    }
    out[t] = y;
}

// ============================================================
// launch
// ============================================================
extern "C" void kernel_launch(void* const* d_in, const int* in_sizes, int n_in,
                              void* d_out, int out_size) {
    const float* x  = (const float*)d_in[0];   // [16384, 512]
    const float* wg = (const float*)d_in[1];   // [512, 8]
    const float* W1 = (const float*)d_in[2];   // [8, 512, 2048]
    const float* b1 = (const float*)d_in[3];   // [8, 2048]
    const float* W2 = (const float*)d_in[4];   // [8, 2048, 1]
    const float* b2 = (const float*)d_in[5];   // [8, 1]
    float* out = (float*)d_out;                // [16384, 1]

    cudaFuncSetAttribute(k_expert, cudaFuncAttributeMaxDynamicSharedMemorySize, SMEM_TOTAL);
    int nsm = 148;
    cudaDeviceGetAttribute(&nsm, cudaDevAttrMultiProcessorCount, 0);

    k_zero<<<1, 32>>>();
    k_transpose<<<dim3(HIDD / 128, 32, NEXP), 256>>>(W1);
    k_gate<<<BTOK / 8, 256>>>(x, wg);
    k_expert<<<2 * nsm, NTHR, SMEM_TOTAL>>>(W2, b1);
    k_combine<<<(BTOK + 255) / 256, 256>>>(out, b2);
}

// round 8
// speedup vs baseline: 1.0627x; 1.0627x over previous
#include <cuda_runtime.h>
#include <cuda_fp16.h>
#include <cstdint>
#include <cstddef>
#include <math.h>

// ---------------- problem constants ----------------
#define BTOK  16384
#define IND   512
#define HIDD  2048
#define NEXP  8
#define NTOP  4

// ---------------- tiling ----------------
#define TM      128               // tokens per block
#define TN      128               // hidden cols per block
#define KBPST   4                 // k-blocks (K=16) per stage => K=64
#define NST     3
#define NKCH    8                 // mainloop iterations (512/64)
#define HTILES  (HIDD / TN)       // 16
#define MTILES  (BTOK / TM)       // 128 (worst case)
#define NTHR    256

// packed-fragment stage sizes (fp16)
#define A_BYTES 16384
#define B_BYTES 16384
#define STAGE_BYTES (A_BYTES + B_BYTES)       // 32768
#define SMEM_TOTAL  (NST * STAGE_BYTES)       // 98304  (2 CTAs/SM)

#define A_TILE_BYTES  16384    // one 16-row m-tile: 32 kb x 32 lanes x 16B
#define B_TILE_BYTES  8192     // one 8-col h-tile: 32 kb x 32 lanes x 8B

// transpose-role blocks in k_prep
#define TRN_BLOCKS 4096        // 16 hc x 32 kb x 8 e
#define GATE_BLOCKS (BTOK / 8) // 2048

// ---------------- device scratch ----------------
// A packed (half2 as uint): [e][slot/16][kb][lane][4]
__device__ __align__(1024) uint32_t g_xcu[(size_t)NEXP * BTOK * IND / 2];
// B packed (half2 as uint): [e][h/8][kb][lane][2]
__device__ __align__(1024) uint32_t g_w1u[(size_t)NEXP * HIDD * IND / 2];
__device__ int   g_cnt[NEXP];
__device__ int   g_sel[BTOK * NTOP];
__device__ int   g_slot[BTOK * NTOP];
__device__ float g_g4[BTOK * NTOP];
__device__ float g_part[(size_t)NEXP * BTOK * HTILES];

// ---------------- helpers ----------------
__device__ __forceinline__ void cp_async16(uint32_t saddr, const void* gaddr) {
    asm volatile("cp.async.cg.shared.global [%0], [%1], 16;" :: "r"(saddr), "l"(gaddr) : "memory");
}
__device__ __forceinline__ uint32_t smem_u32(const void* p) {
    uint32_t a;
    asm("{ .reg .u64 t; cvta.to.shared.u64 t, %1; cvt.u32.u64 %0, t; }" : "=r"(a) : "l"(p));
    return a;
}
__device__ __forceinline__ void mma_f16(float* c, const uint32_t* a, const uint32_t* b) {
    asm volatile(
        "mma.sync.aligned.m16n8k16.row.col.f32.f16.f16.f32 "
        "{%0,%1,%2,%3}, {%4,%5,%6,%7}, {%8,%9}, {%0,%1,%2,%3};"
        : "+f"(c[0]), "+f"(c[1]), "+f"(c[2]), "+f"(c[3])
        : "r"(a[0]), "r"(a[1]), "r"(a[2]), "r"(a[3]), "r"(b[0]), "r"(b[1]));
}

// ============================================================
// kernel 0: zero counters
// ============================================================
__global__ void k_zero() {
    if (threadIdx.x < NEXP) g_cnt[threadIdx.x] = 0;
}

// ============================================================
// kernel 1 (fused): blocks [0,4096) transpose W1; rest do gating
// ============================================================
__global__ void k_prep(const float* __restrict__ W1,
                       const float* __restrict__ x,
                       const float* __restrict__ wg) {
    __shared__ float tile[16][129];          // transpose role
    __shared__ int   s_cnt[NEXP];            // gate role
    __shared__ int   s_base[NEXP];

    const int tid = threadIdx.x;

    if (blockIdx.x < TRN_BLOCKS) {
        // ------- transpose role: W1 -> packed fp16 B-fragment layout -------
        int hc = blockIdx.x & 15;            // 128-h chunk
        int kb = (blockIdx.x >> 4) & 31;     // K=16 block
        int e  = blockIdx.x >> 9;

        #pragma unroll
        for (int it = 0; it < 8; ++it) {
            int idx = tid + it * 256;
            int kr = idx >> 7, hf = idx & 127;
            tile[kr][hf] = W1[((size_t)e * IND + kb * 16 + kr) * HIDD + hc * 128 + hf];
        }
        __syncthreads();

        size_t base2 = (size_t)e * (HIDD * IND / 2);
        #pragma unroll
        for (int it = 0; it < 4; ++it) {
            int w    = tid + it * 256;
            int h8l  = w >> 6;
            int rem  = w & 63;
            int lane = rem >> 1, rj = rem & 1;
            int grp  = lane >> 2, qid = lane & 3;
            int hl   = h8l * 8 + grp;
            int k0   = rj * 8 + qid * 2;
            __half2 v = __floats2half2_rn(tile[k0][hl], tile[k0 + 1][hl]);
            g_w1u[base2 + (size_t)(hc * 16 + h8l) * 2048 + (kb * 32 + lane) * 2 + rj]
                = *(uint32_t*)&v;
        }
        return;
    }

    // ------- gate role: 8 tokens per block, batched atomics -------
    int wid  = tid >> 5;
    int lane = tid & 31;
    int tok  = (blockIdx.x - TRN_BLOCKS) * 8 + wid;
    const float* xr = x + (size_t)tok * IND;

    if (tid < NEXP) s_cnt[tid] = 0;

    float acc[NEXP];
    #pragma unroll
    for (int e = 0; e < NEXP; ++e) acc[e] = 0.f;
    for (int i = lane; i < IND; i += 32) {
        float xv = xr[i];
        #pragma unroll
        for (int e = 0; e < NEXP; ++e) acc[e] = fmaf(xv, wg[i * NEXP + e], acc[e]);
    }
    #pragma unroll
    for (int off = 16; off > 0; off >>= 1) {
        #pragma unroll
        for (int e = 0; e < NEXP; ++e)
            acc[e] += __shfl_xor_sync(0xFFFFFFFFu, acc[e], off);
    }

    // top-4: strict '>' keeps lowest index on ties (matches jax.lax.top_k)
    int   sel[NTOP];
    float val[NTOP];
    bool  used[NEXP];
    #pragma unroll
    for (int e = 0; e < NEXP; ++e) used[e] = false;
    #pragma unroll
    for (int k = 0; k < NTOP; ++k) {
        float best = -1e30f; int be = 0;
        #pragma unroll
        for (int e = 0; e < NEXP; ++e)
            if (!used[e] && acc[e] > best) { best = acc[e]; be = e; }
        used[be] = true; sel[k] = be; val[k] = best;
    }
    float s = 0.f, gt[NTOP];
    #pragma unroll
    for (int k = 0; k < NTOP; ++k) { gt[k] = expf(val[k] - val[0]); s += gt[k]; }
    float inv = 1.f / s;
    #pragma unroll
    for (int k = 0; k < NTOP; ++k) gt[k] *= inv;

    // batched slot assignment: smem-local offsets, then <=8 global atomics
    __syncthreads();
    int loc[NTOP];
    if (lane == 0) {
        #pragma unroll
        for (int k = 0; k < NTOP; ++k) loc[k] = atomicAdd(&s_cnt[sel[k]], 1);
    }
    __syncthreads();
    if (tid < NEXP && s_cnt[tid] > 0) s_base[tid] = atomicAdd(&g_cnt[tid], s_cnt[tid]);
    __syncthreads();

    int slot[NTOP];
    #pragma unroll
    for (int k = 0; k < NTOP; ++k) {
        int l = __shfl_sync(0xFFFFFFFFu, loc[k], 0);
        slot[k] = s_base[sel[k]] + l;
    }

    if (lane < NTOP) {
        g_sel[tok * NTOP + lane]  = sel[lane];
        g_slot[tok * NTOP + lane] = slot[lane];
        g_g4[tok * NTOP + lane]   = gt[lane];
    }

    // pre-round row to half2 pairs, scatter into packed-fragment layout
    uint32_t hv[8];
    #pragma unroll
    for (int it = 0; it < 8; ++it) {
        int p = lane + it * 32;
        __half2 v = __floats2half2_rn(xr[2 * p], xr[2 * p + 1]);
        hv[it] = *(uint32_t*)&v;
    }
    #pragma unroll
    for (int kk = 0; kk < NTOP; ++kk) {
        int sl = slot[kk];
        size_t base2 = (size_t)sel[kk] * (BTOK * IND / 2) + (size_t)(sl >> 4) * 4096;
        int r = sl & 15, grp = r & 7, rowhalf = r >> 3;
        #pragma unroll
        for (int it = 0; it < 8; ++it) {
            int p     = lane + it * 32;
            int kb    = p >> 3;
            int khalf = (p & 7) >> 2;
            int qid   = p & 3;
            g_xcu[base2 + (size_t)(kb * 32 + grp * 4 + qid) * 4 + rowhalf + 2 * khalf]
                = hv[it];
        }
    }
}

// ============================================================
// kernel 2: expert GEMM fp16 m16n8k16 (fc1 + relu + fc2-partial)
// grid (HTILES, MTILES, NEXP), 256 threads, 2 CTAs/SM
// ============================================================
__device__ __forceinline__ void load_stage(uint32_t sb, int s, int kt, int tid,
                                           const char* Ag, const char* Bg) {
    uint32_t abase = sb + (uint32_t)s * STAGE_BYTES;
    uint32_t bbase = abase + A_BYTES;
    #pragma unroll
    for (int it = 0; it < 4; ++it) {
        int c    = tid + it * NTHR;
        int tile = c >> 7, rem = c & 127;
        cp_async16(abase + (uint32_t)c * 16,
                   Ag + (size_t)tile * A_TILE_BYTES + kt * 2048 + rem * 16);
    }
    #pragma unroll
    for (int it = 0; it < 4; ++it) {
        int c    = tid + it * NTHR;
        int tile = c >> 6, rem = c & 63;
        cp_async16(bbase + (uint32_t)c * 16,
                   Bg + (size_t)tile * B_TILE_BYTES + kt * 1024 + rem * 16);
    }
    asm volatile("cp.async.commit_group;" ::: "memory");
}

__global__ void __launch_bounds__(NTHR, 2)
k_expert(const float* __restrict__ W2, const float* __restrict__ b1) {
    extern __shared__ char smem[];
    const int e     = blockIdx.z;
    const int mtile = blockIdx.y;
    const int ht    = blockIdx.x;
    const int cnt   = g_cnt[e];
    const int m0    = mtile * TM;
    if (m0 >= cnt) return;

    const int tid  = threadIdx.x;
    const int wid  = tid >> 5;
    const int lane = tid & 31;
    const int wm   = wid >> 2;       // 0..1 : rows wm*64
    const int wn   = wid & 3;        // 0..3 : cols wn*32
    const int grp  = lane >> 2;
    const int qid  = lane & 3;

    // epilogue weight prefetch (hides gmem latency behind the mainloop)
    float w2r = 0.f, b1r = 0.f;
    if (tid < TN) {
        w2r = W2[(size_t)e * HIDD + ht * TN + tid];
        b1r = b1[(size_t)e * HIDD + ht * TN + tid];
    }

    uint32_t sb = smem_u32(smem);
    const char* Ag = (const char*)g_xcu + (size_t)e * (BTOK * IND * 2)
                   + (size_t)(m0 >> 4) * A_TILE_BYTES;
    const char* Bg = (const char*)g_w1u + (size_t)e * (HIDD * IND * 2)
                   + (size_t)(ht * (TN / 8)) * B_TILE_BYTES;

    float acc[4][4][4];
    #pragma unroll
    for (int mt = 0; mt < 4; ++mt)
        #pragma unroll
        for (int nt = 0; nt < 4; ++nt)
            #pragma unroll
            for (int r = 0; r < 4; ++r) acc[mt][nt][r] = 0.f;

    load_stage(sb, 0, 0, tid, Ag, Bg);
    load_stage(sb, 1, 1, tid, Ag, Bg);

    for (int kt = 0; kt < NKCH; ++kt) {
        asm volatile("cp.async.wait_group 1;" ::: "memory");
        __syncthreads();
        int kn = kt + 2;
        if (kn < NKCH) load_stage(sb, kn % NST, kn, tid, Ag, Bg);
        else asm volatile("cp.async.commit_group;" ::: "memory");

        const uint4* sA = (const uint4*)(smem + (size_t)(kt % NST) * STAGE_BYTES);
        const uint2* sB = (const uint2*)(smem + (size_t)(kt % NST) * STAGE_BYTES + A_BYTES);

        #pragma unroll
        for (int ks = 0; ks < KBPST; ++ks) {             // 4 K=16 steps
            uint4 af[4];
            uint2 bf[4];
            #pragma unroll
            for (int mt = 0; mt < 4; ++mt)
                af[mt] = sA[((wm * 4 + mt) * 4 + ks) * 32 + lane];
            #pragma unroll
            for (int nt = 0; nt < 4; ++nt)
                bf[nt] = sB[((wn * 4 + nt) * 4 + ks) * 32 + lane];
            #pragma unroll
            for (int mt = 0; mt < 4; ++mt)
                #pragma unroll
                for (int nt = 0; nt < 4; ++nt)
                    mma_f16(acc[mt][nt], (const uint32_t*)&af[mt], (const uint32_t*)&bf[nt]);
        }
    }
    __syncthreads();

    // ---- fused epilogue: relu(h + b1) . W2 over this 128-col tile ----
    float* red = (float*)smem;                 // [TM][4]
    float* w2s = (float*)(smem + TM * 4 * 4);  // [TN]
    float* b1s = w2s + TN;                     // [TN]
    if (tid < TN) {
        w2s[tid] = w2r;
        b1s[tid] = b1r;
    }
    __syncthreads();

    #pragma unroll
    for (int mt = 0; mt < 4; ++mt) {
        #pragma unroll
        for (int rr = 0; rr < 2; ++rr) {
            int row = wm * 64 + mt * 16 + grp + rr * 8;
            float v = 0.f;
            #pragma unroll
            for (int nt = 0; nt < 4; ++nt) {
                int col = wn * 32 + nt * 8 + qid * 2;
                float h0 = fmaxf(acc[mt][nt][rr * 2 + 0] + b1s[col], 0.f);
                float h1 = fmaxf(acc[mt][nt][rr * 2 + 1] + b1s[col + 1], 0.f);
                v = fmaf(h0, w2s[col], v);
                v = fmaf(h1, w2s[col + 1], v);
            }
            v += __shfl_down_sync(0xFFFFFFFFu, v, 2);
            v += __shfl_down_sync(0xFFFFFFFFu, v, 1);
            if (qid == 0) red[row * 4 + wn] = v;
        }
    }
    __syncthreads();

    if (tid < TM) {
        float p = red[tid * 4 + 0] + red[tid * 4 + 1] + red[tid * 4 + 2] + red[tid * 4 + 3];
        g_part[((size_t)e * BTOK + m0 + tid) * HTILES + ht] = p;
    }
}

// ============================================================
// kernel 3: weighted combine
// ============================================================
__global__ void k_combine(float* __restrict__ out, const float* __restrict__ b2) {
    int t = blockIdx.x * blockDim.x + threadIdx.x;
    if (t >= BTOK) return;
    float y = 0.f;
    #pragma unroll
    for (int k = 0; k < NTOP; ++k) {
        int   e = g_sel[t * NTOP + k];
        int   s = g_slot[t * NTOP + k];
        float g = g_g4[t * NTOP + k];
        float p = b2[e];
        const float* pp = &g_part[((size_t)e * BTOK + s) * HTILES];
        #pragma unroll
        for (int h = 0; h < HTILES; ++h) p += pp[h];
        y = fmaf(g, p, y);
    }
    out[t] = y;
}

// ============================================================
// launch
// ============================================================
extern "C" void kernel_launch(void* const* d_in, const int* in_sizes, int n_in,
                              void* d_out, int out_size) {
    const float* x  = (const float*)d_in[0];   // [16384, 512]
    const float* wg = (const float*)d_in[1];   // [512, 8]
    const float* W1 = (const float*)d_in[2];   // [8, 512, 2048]
    const float* b1 = (const float*)d_in[3];   // [8, 2048]
    const float* W2 = (const float*)d_in[4];   // [8, 2048, 1]
    const float* b2 = (const float*)d_in[5];   // [8, 1]
    float* out = (float*)d_out;                // [16384, 1]

    cudaFuncSetAttribute(k_expert, cudaFuncAttributeMaxDynamicSharedMemorySize, SMEM_TOTAL);

    k_zero<<<1, 32>>>();
    k_prep<<<TRN_BLOCKS + GATE_BLOCKS, 256>>>(W1, x, wg);
    k_expert<<<dim3(HTILES, MTILES, NEXP), NTHR, SMEM_TOTAL>>>(W2, b1);
    k_combine<<<(BTOK + 255) / 256, 256>>>(out, b2);
}